// round 8
// baseline (speedup 1.0000x reference)
#include <cuda_runtime.h>
#include <cuda_bf16.h>

// Problem constants
#define BB 32
#define NN 1024
#define FF 128
#define DD 128
#define DK 0.08838834764831843f  // 128^{-0.5}

#define NBLK 128   // 4 chunk-blocks per batch, 256 rows each
#define NTHR 1024  // 32 warps per block
#define ROWS 256   // rows per block

// Scratch
__device__ float  g_spart[BB * 4 * FF];
__device__ float2 g_ls[BB * 4];       // (local max, local sumexp) per chunk
__device__ unsigned g_bar;            // monotonic ticket (replay-safe)

// ---------------------------------------------------------------------------
// Software grid barrier: monotonic ticket. All 128 blocks co-resident
// (1 CTA/SM, 148 SMs, 156KB smem < 228KB).
// ---------------------------------------------------------------------------
__device__ __forceinline__ void grid_barrier() {
    __threadfence();
    __syncthreads();
    if (threadIdx.x == 0) {
        unsigned ticket = atomicAdd(&g_bar, 1u);
        unsigned target = (ticket / NBLK + 1u) * NBLK;
        unsigned cur;
        do {
            asm volatile("ld.global.acquire.gpu.u32 %0, [%1];"
                         : "=r"(cur) : "l"(&g_bar));
        } while (cur < target);
    }
    __syncthreads();
    __threadfence();
}

__global__ __launch_bounds__(NTHR, 1) void k_fused(
        const float* __restrict__ aq,
        const float* __restrict__ mask,
        const float* __restrict__ Wq,
        const float* __restrict__ bq,
        const float* __restrict__ Wk,
        const float* __restrict__ bk,
        const float* __restrict__ Wv,
        const float* __restrict__ bv,
        float* __restrict__ out_attn,
        float* __restrict__ out_ctx) {
    int blk = blockIdx.x;
    int b   = blk >> 2;        // batch
    int ch  = blk & 3;         // 256-row chunk
    int tid = threadIdx.x;
    int lane = tid & 31;
    int warp = tid >> 5;       // 0..31, owns 8 rows of the chunk

    extern __shared__ float4 aq_sh4[];   // [ROWS*32] = 128 KB: this block's rows

    __shared__ float4 sh4[32][32];       // 16 KB reduce scratch
    __shared__ float  s_sh[FF];
    __shared__ float  ksum_sh[DD];
    __shared__ float  wvec_sh[FF];
    __shared__ float  t_sh[FF];
    __shared__ float  l_sh[ROWS];        // masked logits (own rows)
    __shared__ float  m_sh[ROWS];        // mask (own rows)
    __shared__ float  w_sh[ROWS];        // weights (own rows)
    __shared__ float  ctx_part[8][DD];   // 4 KB
    __shared__ float  red[32];
    __shared__ float2 ls4_sh[4];
    __shared__ float  bc[2];

    const float4* aq4 = reinterpret_cast<const float4*>(aq);
    int rloc0 = warp * 8;                         // warp's first local row
    int row0  = ch * ROWS + rloc0;                // row within batch
    const float4* base = aq4 + ((size_t)b * NN + row0) * (FF / 4);

    // ---- P0: zero out_ctx (poisoned by harness); load own mask ----
    if (ch == 0 && tid < DD) out_ctx[b * DD + tid] = 0.f;
    if (tid < ROWS) m_sh[tid] = mask[(size_t)b * NN + ch * ROWS + tid];

    // ---- P1: DRAM -> smem stage + row-sum partials ----
    {
        float4 v[8];
#pragma unroll
        for (int jj = 0; jj < 8; jj++)
            v[jj] = base[jj * (FF / 4) + lane];
#pragma unroll
        for (int jj = 0; jj < 8; jj++)
            aq_sh4[(rloc0 + jj) * 32 + lane] = v[jj];
        float4 acc = v[0];
#pragma unroll
        for (int jj = 1; jj < 8; jj++) {
            acc.x += v[jj].x; acc.y += v[jj].y;
            acc.z += v[jj].z; acc.w += v[jj].w;
        }
        sh4[warp][lane] = acc;
        __syncthreads();
        if (warp < 4) {
            float4 r = sh4[warp * 8][lane];
#pragma unroll
            for (int w = 1; w < 8; w++) {
                float4 x = sh4[warp * 8 + w][lane];
                r.x += x.x; r.y += x.y; r.z += x.z; r.w += x.w;
            }
            sh4[warp][lane] = r;
        }
        __syncthreads();
        if (warp == 0) {
            float4 r = sh4[0][lane];
#pragma unroll
            for (int w = 1; w < 4; w++) {
                float4 x = sh4[w][lane];
                r.x += x.x; r.y += x.y; r.z += x.z; r.w += x.w;
            }
            reinterpret_cast<float4*>(&g_spart[(b * 4 + ch) * FF])[lane] = r;
        }
    }

    grid_barrier();   // ==== barrier 1: all g_spart ready ====

    // ---- P2: (redundant per block) s, ksum, wvec, cbias ----
    if (tid < FF) {
        float s = 0.f;
#pragma unroll
        for (int c2 = 0; c2 < 4; c2++)
            s += g_spart[(b * 4 + c2) * FF + tid];
        s_sh[tid] = s;
    }
    __syncthreads();
    if (tid < DD) {
        float acc = 0.f;
#pragma unroll 8
        for (int f = 0; f < FF; f++)
            acc += s_sh[f] * Wk[(size_t)f * DD + tid];
        ksum_sh[tid] = acc + (float)NN * bk[tid];
    }
    __syncthreads();
    {
#pragma unroll
        for (int j = 0; j < 4; j++) {
            int f = warp * 4 + j;
            float p = 0.f;
#pragma unroll
            for (int dd = lane; dd < DD; dd += 32)
                p += Wq[(size_t)f * DD + dd] * ksum_sh[dd];
            for (int off = 16; off; off >>= 1)
                p += __shfl_xor_sync(0xffffffffu, p, off);
            if (lane == 0) wvec_sh[f] = p;
        }
    }
    if (warp == 0) {
        float p = 0.f;
#pragma unroll
        for (int dd = lane; dd < DD; dd += 32)
            p += bq[dd] * ksum_sh[dd];
        for (int off = 16; off; off >>= 1)
            p += __shfl_xor_sync(0xffffffffu, p, off);
        if (lane == 0) bc[0] = p;
    }
    __syncthreads();

    // ---- P3: masked logits from smem; local (max, sumexp) -> g_ls ----
    {
        float4 wv4 = reinterpret_cast<const float4*>(wvec_sh)[lane];
        float cb = bc[0];
        float mine = 0.f;
#pragma unroll
        for (int jj = 0; jj < 8; jj++) {
            float4 x = aq_sh4[(rloc0 + jj) * 32 + lane];
            float d = x.x * wv4.x + x.y * wv4.y + x.z * wv4.z + x.w * wv4.w;
            for (int off = 16; off; off >>= 1)
                d += __shfl_xor_sync(0xffffffffu, d, off);
            if (lane == jj) mine = DK * (d + cb);
        }
        if (lane < 8) {
            float m = m_sh[rloc0 + lane];
            l_sh[rloc0 + lane] = (m != 0.f) ? mine : -1e9f;
        }
    }
    __syncthreads();
    // block-local max over 256 logits
    if (tid < ROWS) {
        float l = l_sh[tid];
        float mx = l;
        for (int off = 16; off; off >>= 1)
            mx = fmaxf(mx, __shfl_xor_sync(0xffffffffu, mx, off));
        if (lane == 0) red[warp] = mx;
    }
    __syncthreads();
    if (warp == 0) {
        float m2 = (lane < 8) ? red[lane] : -3.4e38f;
        for (int off = 4; off; off >>= 1)
            m2 = fmaxf(m2, __shfl_xor_sync(0xffffffffu, m2, off));
        if (lane == 0) bc[1] = m2;
    }
    __syncthreads();
    {
        float lmax = bc[1];
        float e = 0.f;
        if (tid < ROWS) e = expf(l_sh[tid] - lmax);
        if (tid < ROWS) {
            float s = e;
            for (int off = 16; off; off >>= 1)
                s += __shfl_xor_sync(0xffffffffu, s, off);
            if (lane == 0) red[warp] = s;
        }
        __syncthreads();
        if (warp == 0) {
            float s2 = (lane < 8) ? red[lane] : 0.f;
            for (int off = 4; off; off >>= 1)
                s2 += __shfl_xor_sync(0xffffffffu, s2, off);
            if (lane == 0)
                g_ls[b * 4 + ch] = make_float2(lmax, s2);
        }
    }

    grid_barrier();   // ==== barrier 2: all (lmax, lsum) ready ====

    // ---- P4: combine chunk stats; attn + w for own rows only ----
    if (tid < 4) ls4_sh[tid] = g_ls[b * 4 + tid];
    __syncthreads();
    {
        float gmax = ls4_sh[0].x;
#pragma unroll
        for (int i = 1; i < 4; i++) gmax = fmaxf(gmax, ls4_sh[i].x);
        float gsum = 0.f;
#pragma unroll
        for (int i = 0; i < 4; i++)
            gsum += expf(ls4_sh[i].x - gmax) * ls4_sh[i].y;
        float inv = 1.0f / gsum;

        if (tid < ROWS) {
            float attn = expf(l_sh[tid] - gmax) * inv;
            out_attn[(size_t)b * NN + ch * ROWS + tid] = attn;
            float w = m_sh[tid] * attn;
            w_sh[tid] = w;
            // block-local wsum partial
            float ws = w;
            for (int off = 16; off; off >>= 1)
                ws += __shfl_xor_sync(0xffffffffu, ws, off);
            if (lane == 0) red[warp] = ws;
        }
        __syncthreads();
        if (warp == 0) {
            float s2 = (lane < 8) ? red[lane] : 0.f;
            for (int off = 4; off; off >>= 1)
                s2 += __shfl_xor_sync(0xffffffffu, s2, off);
            if (lane == 0) bc[0] = s2;          // wsum_part
        }
        __syncthreads();
    }

    // ---- P5: weighted row-sum from smem + partial ctx matvec ----
    {
        float4 acc = make_float4(0.f, 0.f, 0.f, 0.f);
#pragma unroll
        for (int jj = 0; jj < 8; jj++) {
            float4 x = aq_sh4[(rloc0 + jj) * 32 + lane];
            float w = w_sh[rloc0 + jj];
            acc.x += w * x.x; acc.y += w * x.y;
            acc.z += w * x.z; acc.w += w * x.w;
        }
        sh4[warp][lane] = acc;
        __syncthreads();
        if (warp < 4) {
            float4 r = sh4[warp * 8][lane];
#pragma unroll
            for (int w = 1; w < 8; w++) {
                float4 x = sh4[warp * 8 + w][lane];
                r.x += x.x; r.y += x.y; r.z += x.z; r.w += x.w;
            }
            sh4[warp][lane] = r;
        }
        __syncthreads();
        if (warp == 0) {
            float4 r = sh4[0][lane];
#pragma unroll
            for (int w = 1; w < 4; w++) {
                float4 x = sh4[w][lane];
                r.x += x.x; r.y += x.y; r.z += x.z; r.w += x.w;
            }
            reinterpret_cast<float4*>(t_sh)[lane] = r;
        }
        __syncthreads();

        // ctx matvec: 8 f-partials x 128 d across all 1024 threads
        {
            int d = tid & 127;
            int part = tid >> 7;
            float acc2 = 0.f;
#pragma unroll
            for (int f = part * 16; f < part * 16 + 16; f++)
                acc2 += t_sh[f] * Wv[(size_t)f * DD + d];
            ctx_part[part][d] = acc2;
        }
        __syncthreads();
        if (tid < DD) {
            float accd = 0.f;
#pragma unroll
            for (int p = 0; p < 8; p++)
                accd += ctx_part[p][tid];
            accd += bc[0] * bv[tid];            // own wsum partial * bv
            atomicAdd(&out_ctx[(size_t)b * DD + tid], accd);
        }
    }
}

// ---------------------------------------------------------------------------
// Inputs: atom_query, mask, Wq, bq, Wk, bk, Wv, bv
// Output: attn [B*N] then context [B*D], float32.
// ---------------------------------------------------------------------------
extern "C" void kernel_launch(void* const* d_in, const int* in_sizes, int n_in,
                              void* d_out, int out_size) {
    const float* aq   = (const float*)d_in[0];
    const float* mask = (const float*)d_in[1];
    const float* Wq   = (const float*)d_in[2];
    const float* bq   = (const float*)d_in[3];
    const float* Wk   = (const float*)d_in[4];
    const float* bk   = (const float*)d_in[5];
    const float* Wv   = (const float*)d_in[6];
    const float* bv   = (const float*)d_in[7];

    float* out_attn = (float*)d_out;
    float* out_ctx  = out_attn + (size_t)BB * NN;

    const int dyn_smem = ROWS * FF * sizeof(float);   // 128 KB
    cudaFuncSetAttribute(k_fused,
                         cudaFuncAttributeMaxDynamicSharedMemorySize, dyn_smem);

    k_fused<<<NBLK, NTHR, dyn_smem>>>(aq, mask, Wq, bq, Wk, bk, Wv, bv,
                                      out_attn, out_ctx);
}